// round 15
// baseline (speedup 1.0000x reference)
#include <cuda_runtime.h>
#include <cuda_bf16.h>
#include <cstdint>

// Problem constants
#define BB 512
#define TT 1024
#define DD 64
#define HH 128
#define GG 384   // 3*H
#define NTHR 768

// Scratch for precomputed input gates, layout [b][t][g]
__device__ float g_xg[(size_t)BB * TT * GG];

// ---------- packed fp32x2 helpers ----------
__device__ __forceinline__ unsigned long long ffma2(unsigned long long a,
                                                    unsigned long long b,
                                                    unsigned long long c) {
    unsigned long long d;
    asm("fma.rn.f32x2 %0, %1, %2, %3;" : "=l"(d) : "l"(a), "l"(b), "l"(c));
    return d;
}
__device__ __forceinline__ float f2sum(unsigned long long v) {
    float lo, hi;
    asm("mov.b64 {%0, %1}, %2;" : "=f"(lo), "=f"(hi) : "l"(v));
    return lo + hi;
}
__device__ __forceinline__ float tanh_fast(float x) {
    float y;
    asm("tanh.approx.f32 %0, %1;" : "=f"(y) : "f"(x));
    return y;
}
__device__ __forceinline__ float sigmoid_fast(float x) {
    return fmaf(tanh_fast(0.5f * x), 0.5f, 0.5f);
}

// ---------- mma.sync / ldmatrix helpers (compute_103-safe, sm_80 PTX) ----------
__device__ __forceinline__ uint32_t smem_u32(const void* p) {
    uint32_t a;
    asm("{ .reg .u64 t; cvta.to.shared.u64 t, %1; cvt.u32.u64 %0, t; }"
        : "=r"(a) : "l"(p));
    return a;
}
__device__ __forceinline__ void ldm_x4(uint32_t& r0, uint32_t& r1,
                                       uint32_t& r2, uint32_t& r3, uint32_t a) {
    asm volatile("ldmatrix.sync.aligned.m8n8.x4.shared.b16 {%0,%1,%2,%3}, [%4];"
                 : "=r"(r0), "=r"(r1), "=r"(r2), "=r"(r3) : "r"(a));
}
__device__ __forceinline__ void ldm_x2(uint32_t& r0, uint32_t& r1, uint32_t a) {
    asm volatile("ldmatrix.sync.aligned.m8n8.x2.shared.b16 {%0,%1}, [%2];"
                 : "=r"(r0), "=r"(r1) : "r"(a));
}
__device__ __forceinline__ void mma_bf16(float* c, const uint32_t* a,
                                         const uint32_t* b) {
    asm volatile(
        "mma.sync.aligned.m16n8k16.row.col.f32.bf16.bf16.f32 "
        "{%0,%1,%2,%3}, {%4,%5,%6,%7}, {%8,%9}, {%0,%1,%2,%3};"
        : "+f"(c[0]), "+f"(c[1]), "+f"(c[2]), "+f"(c[3])
        : "r"(a[0]), "r"(a[1]), "r"(a[2]), "r"(a[3]), "r"(b[0]), "r"(b[1]));
}

// smem layout (byte offsets; row stride 72 bf16 = 144B, conflict-free ldmatrix)
// B hi and lo share ONE buffer (staged sequentially) -> ~94 KB -> 2 CTAs/SM.
#define XS_AHI   0
#define XS_ALO   18432                      // 128*144
#define XS_BBUF  36864                      // 384*144 = 55296, reused hi->lo
#define XS_BIAS  92160
#define XS_TOTAL (XS_BIAS + GG * 4 + 128)

// ============================================================================
// Kernel 1: xg via HMMA. 2 CTAs/SM (B hi/lo staged through one buffer).
// Grid 1024 = (b, 2 halves of 512 tokens); 256 threads (8 warps).
// Fragment math byte-identical to R13/R14 (verified correct).
// ============================================================================
__global__ void __launch_bounds__(256, 2)
xg_mma(const float* __restrict__ x,
       const float* __restrict__ w_ih,
       const float* __restrict__ b_ih) {
    extern __shared__ __align__(128) char sm[];
    const uint32_t smb = smem_u32(sm);
    const int tid  = threadIdx.x;
    const int wi   = tid >> 5;
    const int lane = tid & 31;

    const int b     = blockIdx.x >> 1;
    const int tbase = (blockIdx.x & 1) << 9;   // 0 or 512

    // ---- stage B-hi into BBUF ----
    for (int i = tid; i < GG * DD; i += 256) {
        int n = i >> 6, k = i & 63;
        float v = w_ih[(size_t)n * DD + k];
        *reinterpret_cast<__nv_bfloat16*>(sm + XS_BBUF + (n * 72 + k) * 2) =
            __float2bfloat16_rn(v);
    }
    for (int i = tid; i < GG; i += 256)
        reinterpret_cast<float*>(sm + XS_BIAS)[i] = b_ih[i];
    __syncthreads();

    // ---- preload B-hi fragments ----
    uint32_t bh[6][4][2], bl[6][4][2];
    const int brow = 48 * wi + (lane & 7);
    const int bcol = ((lane >> 3) & 1) * 16;  // bytes
#pragma unroll
    for (int j = 0; j < 6; j++)
#pragma unroll
        for (int kk = 0; kk < 4; kk++)
            ldm_x2(bh[j][kk][0], bh[j][kk][1],
                   smb + XS_BBUF + (brow + 8 * j) * 144 + bcol + kk * 32);
    __syncthreads();  // done reading hi before overwrite

    // ---- stage B-lo into BBUF (overwrite) ----
    for (int i = tid; i < GG * DD; i += 256) {
        int n = i >> 6, k = i & 63;
        float v = w_ih[(size_t)n * DD + k];
        __nv_bfloat16 hi = __float2bfloat16_rn(v);
        *reinterpret_cast<__nv_bfloat16*>(sm + XS_BBUF + (n * 72 + k) * 2) =
            __float2bfloat16_rn(v - __bfloat162float(hi));
    }
    __syncthreads();

    // ---- preload B-lo fragments ----
#pragma unroll
    for (int j = 0; j < 6; j++)
#pragma unroll
        for (int kk = 0; kk < 4; kk++)
            ldm_x2(bl[j][kk][0], bl[j][kk][1],
                   smb + XS_BBUF + (brow + 8 * j) * 144 + bcol + kk * 32);

    float2 bias[6];
    {
        const int c0 = 2 * (lane & 3);
#pragma unroll
        for (int j = 0; j < 6; j++)
            bias[j] = *reinterpret_cast<const float2*>(
                sm + XS_BIAS + (48 * wi + 8 * j + c0) * 4);
    }

    const int arow = lane & 15;
    const int acol = ((lane >> 4) & 1) * 16;  // bytes
    const int drow = lane >> 2;
    const int dcol = 2 * (lane & 3);

#pragma unroll 1
    for (int ch = 0; ch < 4; ch++) {
        const int t0 = tbase + (ch << 7);

        // ---- stage A chunk: x[b][t0..+128][0..64] -> bf16 hi/lo ----
        for (int i = tid; i < 128 * DD; i += 256) {
            int tok = i >> 6, c = i & 63;
            float v = x[((size_t)b * TT + t0 + tok) * DD + c];
            __nv_bfloat16 hi = __float2bfloat16_rn(v);
            __nv_bfloat16 lo = __float2bfloat16_rn(v - __bfloat162float(hi));
            int off = (tok * 72 + c) * 2;
            *reinterpret_cast<__nv_bfloat16*>(sm + XS_AHI + off) = hi;
            *reinterpret_cast<__nv_bfloat16*>(sm + XS_ALO + off) = lo;
        }
        __syncthreads();

#pragma unroll 1
        for (int m = 0; m < 8; m++) {
            uint32_t ah[4][4], al[4][4];
#pragma unroll
            for (int kk = 0; kk < 4; kk++) {
                uint32_t a = smb + XS_AHI + (16 * m + arow) * 144 + acol + kk * 32;
                ldm_x4(ah[kk][0], ah[kk][1], ah[kk][2], ah[kk][3], a);
                a = smb + XS_ALO + (16 * m + arow) * 144 + acol + kk * 32;
                ldm_x4(al[kk][0], al[kk][1], al[kk][2], al[kk][3], a);
            }
#pragma unroll
            for (int j = 0; j < 6; j++) {
                float acc[4] = {bias[j].x, bias[j].y, bias[j].x, bias[j].y};
#pragma unroll
                for (int kk = 0; kk < 4; kk++) mma_bf16(acc, ah[kk], bh[j][kk]);
#pragma unroll
                for (int kk = 0; kk < 4; kk++) mma_bf16(acc, al[kk], bh[j][kk]);
#pragma unroll
                for (int kk = 0; kk < 4; kk++) mma_bf16(acc, ah[kk], bl[j][kk]);

                const size_t base =
                    ((size_t)b * TT + t0 + 16 * m + drow) * GG + 48 * wi + 8 * j + dcol;
                *reinterpret_cast<float2*>(g_xg + base) =
                    make_float2(acc[0], acc[1]);
                *reinterpret_cast<float2*>(g_xg + base + 8 * GG) =
                    make_float2(acc[2], acc[3]);
            }
        }
        __syncthreads();  // all warps done with A before restaging
    }
}

// ============================================================================
// Kernel 2: persistent GRU — FROZEN (R13/R14 best: 2203us).
// ============================================================================
__global__ void __launch_bounds__(NTHR, 1)
gru_kernel(const float* __restrict__ mask,
           const float* __restrict__ w_hh,
           const float* __restrict__ b_hh,
           const float* __restrict__ Wo,
           const float* __restrict__ bo,
           float* __restrict__ out) {
    __shared__ __align__(16) float h_s[4][HH];
    __shared__ __align__(16) float P_s[8][4][GG];
    __shared__ float bh_s[GG];
    __shared__ float m_s[4];
    __shared__ float wo_s[2][HH];

    const int tid  = threadIdx.x;
    const int lane = tid & 31;
    const int sw   = tid / 96;
    const int q    = tid - sw * 96;
    const int b0   = blockIdx.x * 4;

    for (int i = tid; i < 4 * HH; i += NTHR) (&h_s[0][0])[i] = 0.0f;
    for (int i = tid; i < 2 * HH; i += NTHR) (&wo_s[0][0])[i] = Wo[i];
    for (int i = tid; i < GG; i += NTHR) bh_s[i] = b_hh[i];

    const int coff = 16 * sw;
    unsigned long long wq[32];
#pragma unroll
    for (int r = 0; r < 4; r++) {
        const unsigned long long* wp = reinterpret_cast<const unsigned long long*>(
            w_hh + (size_t)(4 * q + r) * HH + coff);
#pragma unroll
        for (int j = 0; j < 8; j++) wq[r * 8 + j] = wp[j];
    }

    const int cb = (tid >> 7) & 3;
    const int cj = tid & 127;
    const bool is_cell = tid < 512;

    const float* xg_cell = g_xg + (size_t)(b0 + cb) * TT * GG + cj;
    const float* mp = mask + (size_t)(b0 + (tid & 3)) * TT;
    const float bo0 = bo[0], bo1 = bo[1];

    __syncthreads();

    for (int t = 0; t < TT; t++) {
        float xr_v = 0.f, xz_v = 0.f, xn_v = 0.f;
        if (is_cell) {
            xr_v = xg_cell[0];
            xz_v = xg_cell[HH];
            xn_v = xg_cell[2 * HH];
        }
        if (tid < 4) m_s[tid] = mp[t];

#pragma unroll
        for (int b = 0; b < 4; b++) {
            const ulonglong2* hp =
                reinterpret_cast<const ulonglong2*>(&h_s[b][0] + coff);
            unsigned long long a0 = 0, a1 = 0, a2 = 0, a3 = 0;
#pragma unroll
            for (int i = 0; i < 4; i++) {
                ulonglong2 v = hp[i];
                a0 = ffma2(wq[2 * i],      v.x, a0);
                a0 = ffma2(wq[2 * i + 1],  v.y, a0);
                a1 = ffma2(wq[8 + 2 * i],  v.x, a1);
                a1 = ffma2(wq[9 + 2 * i],  v.y, a1);
                a2 = ffma2(wq[16 + 2 * i], v.x, a2);
                a2 = ffma2(wq[17 + 2 * i], v.y, a2);
                a3 = ffma2(wq[24 + 2 * i], v.x, a3);
                a3 = ffma2(wq[25 + 2 * i], v.y, a3);
            }
            *reinterpret_cast<float4*>(&P_s[sw][b][4 * q]) =
                make_float4(f2sum(a0), f2sum(a1), f2sum(a2), f2sum(a3));
        }
        __syncthreads();

        if (is_cell) {
            float sr = xr_v + bh_s[cj];
            float sz = xz_v + bh_s[cj + HH];
            float sn = bh_s[cj + 2 * HH];
#pragma unroll
            for (int k = 0; k < 8; k++) {
                sr += P_s[k][cb][cj];
                sz += P_s[k][cb][cj + HH];
                sn += P_s[k][cb][cj + 2 * HH];
            }
            float r  = sigmoid_fast(sr);
            float z  = sigmoid_fast(sz);
            float n  = tanh_fast(fmaf(r, sn, xn_v));
            float ho = h_s[cb][cj];
            float hnew = fmaf(z, ho - n, n);
            float m  = m_s[cb];
            h_s[cb][cj] = fmaf(m, hnew - ho, ho);
        }
        __syncthreads();

        if (tid >= 512) {
            int w = (tid - 512) >> 5;
            int b = w >> 1, o = w & 1;
            float pv = 0.0f;
#pragma unroll
            for (int qq = 0; qq < 4; qq++)
                pv = fmaf(h_s[b][lane + 32 * qq], wo_s[o][lane + 32 * qq], pv);
#pragma unroll
            for (int off = 16; off; off >>= 1)
                pv += __shfl_down_sync(0xffffffffu, pv, off);
            if (lane == 0)
                out[(((size_t)(b0 + b)) * TT + t) * 2 + o] = pv + (o ? bo1 : bo0);
        }

        xg_cell += GG;
    }
}

// ============================================================================
extern "C" void kernel_launch(void* const* d_in, const int* in_sizes, int n_in,
                              void* d_out, int out_size) {
    const float* x    = (const float*)d_in[0];
    const float* mask = (const float*)d_in[1];
    const float* w_ih = (const float*)d_in[2];
    const float* w_hh = (const float*)d_in[3];
    const float* b_ih = (const float*)d_in[4];
    const float* b_hh = (const float*)d_in[5];
    const float* Wo   = (const float*)d_in[6];
    const float* bo   = (const float*)d_in[7];
    float* out = (float*)d_out;

    cudaFuncSetAttribute(xg_mma, cudaFuncAttributeMaxDynamicSharedMemorySize,
                         XS_TOTAL);
    xg_mma<<<BB * 2, 256, XS_TOTAL>>>(x, w_ih, b_ih);
    gru_kernel<<<BB / 4, NTHR>>>(mask, w_hh, b_hh, Wo, bo, out);
}

// round 16
// speedup vs baseline: 1.1915x; 1.1915x over previous
#include <cuda_runtime.h>
#include <cuda_bf16.h>
#include <cstdint>

// Problem constants
#define BB 512
#define TT 1024
#define DD 64
#define HH 128
#define GG 384   // 3*H
#define NTHR 768

// Scratch for precomputed input gates, layout [b][t][g]
__device__ float g_xg[(size_t)BB * TT * GG];

// ---------- packed fp32x2 helpers ----------
__device__ __forceinline__ unsigned long long ffma2(unsigned long long a,
                                                    unsigned long long b,
                                                    unsigned long long c) {
    unsigned long long d;
    asm("fma.rn.f32x2 %0, %1, %2, %3;" : "=l"(d) : "l"(a), "l"(b), "l"(c));
    return d;
}
__device__ __forceinline__ float f2sum(unsigned long long v) {
    float lo, hi;
    asm("mov.b64 {%0, %1}, %2;" : "=f"(lo), "=f"(hi) : "l"(v));
    return lo + hi;
}
__device__ __forceinline__ float tanh_fast(float x) {
    float y;
    asm("tanh.approx.f32 %0, %1;" : "=f"(y) : "f"(x));
    return y;
}
__device__ __forceinline__ float sigmoid_fast(float x) {
    return fmaf(tanh_fast(0.5f * x), 0.5f, 0.5f);
}

// ---------- mma.sync / ldmatrix helpers ----------
__device__ __forceinline__ uint32_t smem_u32(const void* p) {
    uint32_t a;
    asm("{ .reg .u64 t; cvta.to.shared.u64 t, %1; cvt.u32.u64 %0, t; }"
        : "=r"(a) : "l"(p));
    return a;
}
__device__ __forceinline__ void ldm_x4(uint32_t& r0, uint32_t& r1,
                                       uint32_t& r2, uint32_t& r3, uint32_t a) {
    asm volatile("ldmatrix.sync.aligned.m8n8.x4.shared.b16 {%0,%1,%2,%3}, [%4];"
                 : "=r"(r0), "=r"(r1), "=r"(r2), "=r"(r3) : "r"(a));
}
__device__ __forceinline__ void ldm_x2(uint32_t& r0, uint32_t& r1, uint32_t a) {
    asm volatile("ldmatrix.sync.aligned.m8n8.x2.shared.b16 {%0,%1}, [%2];"
                 : "=r"(r0), "=r"(r1) : "r"(a));
}
__device__ __forceinline__ void mma_bf16(float* c, const uint32_t* a,
                                         const uint32_t* b) {
    asm volatile(
        "mma.sync.aligned.m16n8k16.row.col.f32.bf16.bf16.f32 "
        "{%0,%1,%2,%3}, {%4,%5,%6,%7}, {%8,%9}, {%0,%1,%2,%3};"
        : "+f"(c[0]), "+f"(c[1]), "+f"(c[2]), "+f"(c[3])
        : "r"(a[0]), "r"(a[1]), "r"(a[2]), "r"(a[3]), "r"(b[0]), "r"(b[1]));
}

// xg smem layout (R14 layout; row stride 72 bf16 = 144B)
#define XS_AHI   0
#define XS_ALO   18432
#define XS_BHI   36864
#define XS_BLO   92160
#define XS_BIAS  147456
#define XS_TOTAL (XS_BIAS + GG * 4 + 128)

// ============================================================================
// Kernel 1: xg via HMMA — R14 math with 16 WARPS (512 thr, 4 warps/SMSP).
// Warp wi owns 24 gates (3 n-tiles); grid 1024 = (b, 2 halves of 512 tokens),
// 4 chunks of 128 tokens per CTA.
// ============================================================================
__global__ void __launch_bounds__(512, 1)
xg_mma(const float* __restrict__ x,
       const float* __restrict__ w_ih,
       const float* __restrict__ b_ih) {
    extern __shared__ __align__(128) char sm[];
    const uint32_t smb = smem_u32(sm);
    const int tid  = threadIdx.x;
    const int wi   = tid >> 5;      // 0..15
    const int lane = tid & 31;

    const int b     = blockIdx.x >> 1;
    const int tbase = (blockIdx.x & 1) << 9;

    // stage B hi/lo (once)
    for (int i = tid; i < GG * DD; i += 512) {
        int n = i >> 6, k = i & 63;
        float v = w_ih[(size_t)n * DD + k];
        __nv_bfloat16 hi = __float2bfloat16_rn(v);
        __nv_bfloat16 lo = __float2bfloat16_rn(v - __bfloat162float(hi));
        int off = (n * 72 + k) * 2;
        *reinterpret_cast<__nv_bfloat16*>(sm + XS_BHI + off) = hi;
        *reinterpret_cast<__nv_bfloat16*>(sm + XS_BLO + off) = lo;
    }
    for (int i = tid; i < GG; i += 512)
        reinterpret_cast<float*>(sm + XS_BIAS)[i] = b_ih[i];
    __syncthreads();

    // preload B fragments: 3 n-tiles x 4 k-steps x {hi,lo}
    uint32_t bh[3][4][2], bl[3][4][2];
    {
        const int brow = 24 * wi + (lane & 7);
        const int bcol = ((lane >> 3) & 1) * 16;
#pragma unroll
        for (int j = 0; j < 3; j++)
#pragma unroll
            for (int kk = 0; kk < 4; kk++) {
                uint32_t a = smb + XS_BHI + (brow + 8 * j) * 144 + bcol + kk * 32;
                ldm_x2(bh[j][kk][0], bh[j][kk][1], a);
                a = smb + XS_BLO + (brow + 8 * j) * 144 + bcol + kk * 32;
                ldm_x2(bl[j][kk][0], bl[j][kk][1], a);
            }
    }
    float2 bias[3];
    {
        const int c0 = 2 * (lane & 3);
#pragma unroll
        for (int j = 0; j < 3; j++)
            bias[j] = *reinterpret_cast<const float2*>(
                sm + XS_BIAS + (24 * wi + 8 * j + c0) * 4);
    }

    const int arow = lane & 15;
    const int acol = ((lane >> 4) & 1) * 16;
    const int drow = lane >> 2;
    const int dcol = 2 * (lane & 3);

#pragma unroll 1
    for (int ch = 0; ch < 4; ch++) {
        const int t0 = tbase + (ch << 7);

        for (int i = tid; i < 128 * DD; i += 512) {
            int tok = i >> 6, c = i & 63;
            float v = x[((size_t)b * TT + t0 + tok) * DD + c];
            __nv_bfloat16 hi = __float2bfloat16_rn(v);
            __nv_bfloat16 lo = __float2bfloat16_rn(v - __bfloat162float(hi));
            int off = (tok * 72 + c) * 2;
            *reinterpret_cast<__nv_bfloat16*>(sm + XS_AHI + off) = hi;
            *reinterpret_cast<__nv_bfloat16*>(sm + XS_ALO + off) = lo;
        }
        __syncthreads();

#pragma unroll 1
        for (int m = 0; m < 8; m++) {
            uint32_t ah[4][4], al[4][4];
#pragma unroll
            for (int kk = 0; kk < 4; kk++) {
                uint32_t a = smb + XS_AHI + (16 * m + arow) * 144 + acol + kk * 32;
                ldm_x4(ah[kk][0], ah[kk][1], ah[kk][2], ah[kk][3], a);
                a = smb + XS_ALO + (16 * m + arow) * 144 + acol + kk * 32;
                ldm_x4(al[kk][0], al[kk][1], al[kk][2], al[kk][3], a);
            }
#pragma unroll
            for (int j = 0; j < 3; j++) {
                float acc[4] = {bias[j].x, bias[j].y, bias[j].x, bias[j].y};
#pragma unroll
                for (int kk = 0; kk < 4; kk++) mma_bf16(acc, ah[kk], bh[j][kk]);
#pragma unroll
                for (int kk = 0; kk < 4; kk++) mma_bf16(acc, al[kk], bh[j][kk]);
#pragma unroll
                for (int kk = 0; kk < 4; kk++) mma_bf16(acc, ah[kk], bl[j][kk]);

                const size_t base =
                    ((size_t)b * TT + t0 + 16 * m + drow) * GG + 24 * wi + 8 * j + dcol;
                *reinterpret_cast<float2*>(g_xg + base) =
                    make_float2(acc[0], acc[1]);
                *reinterpret_cast<float2*>(g_xg + base + 8 * GG) =
                    make_float2(acc[2], acc[3]);
            }
        }
        __syncthreads();
    }
}

// ============================================================================
// Kernel 2: persistent GRU — ONE CTA barrier per step.
// Group sw (96 threads = 3 warps) owns h-cols [16sw,16sw+16):
//   matvec (R9 geometry) -> CTA bar -> warps 0-1: gates for own 16 cols x 4b;
//   warp 2: logits(t-1) -> named bar(96). P/h/mask double-buffered.
// Dynamic smem ~105 KB.
// ============================================================================
#define GD_P   0                      // [2][8][4][384] = 24576 floats
#define GD_H   24576                  // [2][4][128]    = 1024
#define GD_BH  25600                  // [384]
#define GD_WO  25984                  // [256]
#define GD_M   26240                  // [2][4]
#define GD_FLOATS 26248
#define GD_BYTES  (GD_FLOATS * 4)

__global__ void __launch_bounds__(NTHR, 1)
gru_kernel(const float* __restrict__ mask,
           const float* __restrict__ w_hh,
           const float* __restrict__ b_hh,
           const float* __restrict__ Wo,
           const float* __restrict__ bo,
           float* __restrict__ out) {
    extern __shared__ __align__(16) float dsm[];
    float* P  = dsm + GD_P;
    float* hS = dsm + GD_H;
    float* bhS = dsm + GD_BH;
    float* woS = dsm + GD_WO;
    float* mS = dsm + GD_M;

    const int tid  = threadIdx.x;
    const int lane = tid & 31;
    const int sw   = tid / 96;           // group / k-split, warp-uniform
    const int u    = tid - sw * 96;      // 0..95 within group
    const int q    = u;                  // matvec rows 4q..4q+3 (q<96)
    const int coff = 16 * sw;
    const int b0   = blockIdx.x * 4;

    for (int i = tid; i < 2 * 4 * HH; i += NTHR) hS[i] = 0.0f;
    for (int i = tid; i < GG; i += NTHR) bhS[i] = b_hh[i];
    for (int i = tid; i < 2 * HH; i += NTHR) woS[i] = Wo[i];

    // weights: rows 4q..4q+3, cols [16sw,+16) -> 32 ULL (64 regs)
    unsigned long long wq[32];
#pragma unroll
    for (int r = 0; r < 4; r++) {
        const unsigned long long* wp = reinterpret_cast<const unsigned long long*>(
            w_hh + (size_t)(4 * q + r) * HH + coff);
#pragma unroll
        for (int j = 0; j < 8; j++) wq[r * 8 + j] = wp[j];
    }

    // gate-cell assignment (u < 64): batch gb, column gc (own group's cols)
    const int gb = u >> 4;
    const int gc = coff + (u & 15);
    const bool is_cell = u < 64;
    // logits assignment (u >= 64, warp 2 of group): (b,o) = (sw>>1, sw&1)
    const int lb = sw >> 1, lo_ = sw & 1;

    const float* xg_cell = g_xg + (size_t)(b0 + gb) * TT * GG + gc;
    const float* mp = mask + (size_t)(b0 + (tid & 3)) * TT;
    const float bo0 = bo[0], bo1 = bo[1];

    __syncthreads();

    for (int t = 0; t < TT; t++) {
        const int pp = t & 1;
        float* Pw = P + (size_t)pp * 12288;  // this step's P buffer

        // ---- prefetch xg + mask (hidden under matvec) ----
        float xr_v = 0.f, xz_v = 0.f, xn_v = 0.f;
        if (is_cell) {
            xr_v = xg_cell[0];
            xz_v = xg_cell[HH];
            xn_v = xg_cell[2 * HH];
        }
        if (tid < 4) mS[pp * 4 + tid] = mp[t];

        // ---- matvec on own h slice (h buffer pp) ----
        const float* hb = hS + pp * 4 * HH + coff;
#pragma unroll
        for (int b = 0; b < 4; b++) {
            const ulonglong2* hp =
                reinterpret_cast<const ulonglong2*>(hb + b * HH);
            unsigned long long a0 = 0, a1 = 0, a2 = 0, a3 = 0;
#pragma unroll
            for (int i = 0; i < 4; i++) {
                ulonglong2 v = hp[i];
                a0 = ffma2(wq[2 * i],      v.x, a0);
                a0 = ffma2(wq[2 * i + 1],  v.y, a0);
                a1 = ffma2(wq[8 + 2 * i],  v.x, a1);
                a1 = ffma2(wq[9 + 2 * i],  v.y, a1);
                a2 = ffma2(wq[16 + 2 * i], v.x, a2);
                a2 = ffma2(wq[17 + 2 * i], v.y, a2);
                a3 = ffma2(wq[24 + 2 * i], v.x, a3);
                a3 = ffma2(wq[25 + 2 * i], v.y, a3);
            }
            *reinterpret_cast<float4*>(Pw + (sw * 4 + b) * GG + 4 * q) =
                make_float4(f2sum(a0), f2sum(a1), f2sum(a2), f2sum(a3));
        }
        __syncthreads();   // all P partials visible

        if (is_cell) {
            // ---- gate for own column gc, batch gb ----
            float sr = xr_v + bhS[gc];
            float sz = xz_v + bhS[gc + HH];
            float sn = bhS[gc + 2 * HH];
#pragma unroll
            for (int k = 0; k < 8; k++) {
                const float* Pk = Pw + (k * 4 + gb) * GG;
                sr += Pk[gc];
                sz += Pk[gc + HH];
                sn += Pk[gc + 2 * HH];
            }
            float r  = sigmoid_fast(sr);
            float z  = sigmoid_fast(sz);
            float n  = tanh_fast(fmaf(r, sn, xn_v));
            float ho = hS[pp * 4 * HH + gb * HH + gc];
            float hnew = fmaf(z, ho - n, n);
            float m  = mS[pp * 4 + gb];
            hS[(pp ^ 1) * 4 * HH + gb * HH + gc] = fmaf(m, hnew - ho, ho);
        } else if (t > 0) {
            // ---- logits(t-1): h(t-1) lives in buffer pp ----
            const float* hv = hS + pp * 4 * HH + lb * HH;
            float pv = 0.0f;
#pragma unroll
            for (int qq = 0; qq < 4; qq++)
                pv = fmaf(hv[lane + 32 * qq], woS[lo_ * HH + lane + 32 * qq], pv);
#pragma unroll
            for (int off = 16; off; off >>= 1)
                pv += __shfl_down_sync(0xffffffffu, pv, off);
            if (lane == 0)
                out[(((size_t)(b0 + lb)) * TT + (t - 1)) * 2 + lo_] =
                    pv + (lo_ ? bo1 : bo0);
        }

        // group-local sync: own h slice complete before next matvec
        asm volatile("bar.sync %0, %1;" :: "r"(sw + 1), "r"(96) : "memory");

        xg_cell += GG;
    }

    // final logits for t = TT-1: h(TT-1) in buffer ((TT-1)&1)^1 = 0
    __syncthreads();
    if (u >= 64) {
        const float* hv = hS + 0 * 4 * HH + lb * HH;
        float pv = 0.0f;
#pragma unroll
        for (int qq = 0; qq < 4; qq++)
            pv = fmaf(hv[lane + 32 * qq], woS[lo_ * HH + lane + 32 * qq], pv);
#pragma unroll
        for (int off = 16; off; off >>= 1)
            pv += __shfl_down_sync(0xffffffffu, pv, off);
        if (lane == 0)
            out[(((size_t)(b0 + lb)) * TT + (TT - 1)) * 2 + lo_] =
                pv + (lo_ ? bo1 : bo0);
    }
}

// ============================================================================
extern "C" void kernel_launch(void* const* d_in, const int* in_sizes, int n_in,
                              void* d_out, int out_size) {
    const float* x    = (const float*)d_in[0];
    const float* mask = (const float*)d_in[1];
    const float* w_ih = (const float*)d_in[2];
    const float* w_hh = (const float*)d_in[3];
    const float* b_ih = (const float*)d_in[4];
    const float* b_hh = (const float*)d_in[5];
    const float* Wo   = (const float*)d_in[6];
    const float* bo   = (const float*)d_in[7];
    float* out = (float*)d_out;

    cudaFuncSetAttribute(xg_mma, cudaFuncAttributeMaxDynamicSharedMemorySize,
                         XS_TOTAL);
    cudaFuncSetAttribute(gru_kernel, cudaFuncAttributeMaxDynamicSharedMemorySize,
                         GD_BYTES);
    xg_mma<<<BB * 2, 512, XS_TOTAL>>>(x, w_ih, b_ih);
    gru_kernel<<<BB / 4, NTHR, GD_BYTES>>>(mask, w_hh, b_hh, Wo, bo, out);
}